// round 6
// baseline (speedup 1.0000x reference)
#include <cuda_runtime.h>
#include <cuda_fp16.h>
#include <math.h>
#include <stdint.h>

// Problem constants
#define BB 16
#define QQ 64
#define CC 512
#define DD 512
#define D4 2048
#define MTOT (BB*CC)   // 8192

// Scratch (device globals: allocation-free rule)
__device__ float g_m[BB*CC];
__device__ float g_attn[BB*CC];
__device__ float g_h[BB*DD];
__device__ float g_u[(size_t)BB*CC*DD];                      // 16.8 MB
__device__ __align__(16) __half g_Ahi[(size_t)MTOT*D4];      // 32 MB
__device__ __align__(16) __half g_Alo[(size_t)MTOT*D4];      // 32 MB
__device__ __align__(16) __half g_Bhi[(size_t)D4*D4];        // 8 MB

__device__ __forceinline__ uint32_t smem_u32(const void* p) {
    uint32_t a;
    asm("{ .reg .u64 t; cvta.to.shared.u64 t, %1; cvt.u32.u64 %0, t; }"
        : "=r"(a) : "l"(p));
    return a;
}

#define LDSM4(r, addr) \
    asm volatile("ldmatrix.sync.aligned.m8n8.x4.shared.b16 {%0,%1,%2,%3}, [%4];" \
        : "=r"((r)[0]), "=r"((r)[1]), "=r"((r)[2]), "=r"((r)[3]) : "r"(addr))

#define CP16(dst, src) \
    asm volatile("cp.async.cg.shared.global [%0], [%1], 16;" \
        :: "r"(dst), "l"(src) : "memory")

__device__ __forceinline__ void mma16816(float* d, const uint32_t* a,
                                         uint32_t b0, uint32_t b1) {
    asm volatile(
        "mma.sync.aligned.m16n8k16.row.col.f32.f16.f16.f32 "
        "{%0,%1,%2,%3}, {%4,%5,%6,%7}, {%8,%9}, {%0,%1,%2,%3};"
        : "+f"(d[0]), "+f"(d[1]), "+f"(d[2]), "+f"(d[3])
        : "r"(a[0]), "r"(a[1]), "r"(a[2]), "r"(a[3]), "r"(b0), "r"(b1));
}

// fp16 two-term split: packs (x,y) hi and lo pairs
__device__ __forceinline__ void split2h(float x, float y, uint32_t& hi, uint32_t& lo) {
    __half hx = __float2half_rn(x);
    __half hy = __float2half_rn(y);
    __half lx = __float2half_rn(x - __half2float(hx));
    __half ly = __float2half_rn(y - __half2float(hy));
    hi = ((uint32_t)__half_as_ushort(hy) << 16) | (uint32_t)__half_as_ushort(hx);
    lo = ((uint32_t)__half_as_ushort(ly) << 16) | (uint32_t)__half_as_ushort(lx);
}

// ---------------------------------------------------------------------------
// Kernel 1: per (b, 64-c-tile): row-dots (cq/qq) + sim tile + softmax + u_tilde
// ---------------------------------------------------------------------------
__global__ __launch_bounds__(256) void k_sim_u(
    const float* __restrict__ questions,
    const float* __restrict__ contexts,
    const float* __restrict__ sim_w) {
    __shared__ float sh[4224 + 4352];
    __shared__ float s_cq[64], s_qq[64];
    int b  = blockIdx.x >> 3;
    int ct = blockIdx.x & 7;
    int tid = threadIdx.x;
    int tx = tid & 15, ty = tid >> 4;
    int wid = tid >> 5, lane = tid & 31;

    const float* wp  = sim_w + 2*DD;
    const float* ctx = contexts + ((size_t)b*CC + ct*64) * DD;
    const float* qs  = questions + (size_t)b*QQ*DD;

    // Fused row-dots: warps 0-3 -> cq (ctx . w_c), warps 4-7 -> qq (q . w_q)
    {
        bool isQ = wid >= 4;
        const float* wv = isQ ? (sim_w + DD) : sim_w;
        #pragma unroll
        for (int r = 0; r < 16; r++) {
            int row = (wid & 3) * 16 + r;
            const float* src = isQ ? (qs + (size_t)row*DD) : (ctx + (size_t)row*DD);
            float s = 0.f;
            #pragma unroll 4
            for (int d = lane; d < DD; d += 32) s += src[d] * wv[d];
            #pragma unroll
            for (int o = 16; o > 0; o >>= 1) s += __shfl_xor_sync(0xffffffffu, s, o);
            if (lane == 0) (isQ ? s_qq : s_cq)[row] = s;
        }
    }

    float acc[4][4];
    #pragma unroll
    for (int i = 0; i < 4; i++)
        #pragma unroll
        for (int j = 0; j < 4; j++) acc[i][j] = 0.f;

    float* s_a = sh;
    float* s_b = sh + 2048;

    for (int k0 = 0; k0 < DD; k0 += 32) {
        __syncthreads();
        #pragma unroll
        for (int i = 0; i < 2; i++) {
            int li  = tid*2 + i;
            int row = li >> 3;
            int kq  = li & 7;
            float4 av = *(const float4*)(ctx + (size_t)row*DD + k0 + kq*4);
            float4 wv = *(const float4*)(wp + k0 + kq*4);
            s_a[(kq*4+0)*64 + row] = av.x * wv.x;
            s_a[(kq*4+1)*64 + row] = av.y * wv.y;
            s_a[(kq*4+2)*64 + row] = av.z * wv.z;
            s_a[(kq*4+3)*64 + row] = av.w * wv.w;
            float4 qv = *(const float4*)(qs + (size_t)row*DD + k0 + kq*4);
            s_b[(kq*4+0)*64 + row] = qv.x;
            s_b[(kq*4+1)*64 + row] = qv.y;
            s_b[(kq*4+2)*64 + row] = qv.z;
            s_b[(kq*4+3)*64 + row] = qv.w;
        }
        __syncthreads();
        #pragma unroll
        for (int k = 0; k < 32; k++) {
            float4 av = *(float4*)&s_a[k*64 + ty*4];
            float4 bv = *(float4*)&s_b[k*64 + tx*4];
            float a4[4] = {av.x, av.y, av.z, av.w};
            float b4[4] = {bv.x, bv.y, bv.z, bv.w};
            #pragma unroll
            for (int i = 0; i < 4; i++)
                #pragma unroll
                for (int j = 0; j < 4; j++) acc[i][j] += a4[i] * b4[j];
        }
    }
    __syncthreads();

    float* s_sim = sh;
    #pragma unroll
    for (int i = 0; i < 4; i++) {
        float cqv = s_cq[ty*4 + i];
        #pragma unroll
        for (int j = 0; j < 4; j++) {
            float qqv = s_qq[tx*4 + j];
            s_sim[(ty*4+i)*66 + tx*4 + j] = acc[i][j] + cqv + qqv;
        }
    }
    __syncthreads();

    #pragma unroll
    for (int rr = 0; rr < 8; rr++) {
        int r = wid*8 + rr;
        float v0 = s_sim[r*66 + lane];
        float v1 = s_sim[r*66 + 32 + lane];
        float mx = fmaxf(v0, v1);
        #pragma unroll
        for (int o = 16; o > 0; o >>= 1) mx = fmaxf(mx, __shfl_xor_sync(0xffffffffu, mx, o));
        float e0 = __expf(v0 - mx), e1 = __expf(v1 - mx);
        float sm = e0 + e1;
        #pragma unroll
        for (int o = 16; o > 0; o >>= 1) sm += __shfl_xor_sync(0xffffffffu, sm, o);
        float inv = 1.f / sm;
        s_sim[r*66 + lane]      = e0 * inv;
        s_sim[r*66 + 32 + lane] = e1 * inv;
        if (lane == 0) g_m[b*CC + ct*64 + r] = mx;
    }
    __syncthreads();

    float* s_q2 = sh + 4224;
    for (int d0 = 0; d0 < DD; d0 += 64) {
        #pragma unroll
        for (int i = 0; i < 4; i++) {
            int li  = tid + i*256;
            int row = li >> 4;
            int dq  = li & 15;
            float4 qv = *(const float4*)(qs + (size_t)row*DD + d0 + dq*4);
            *(float4*)&s_q2[row*68 + dq*4] = qv;
        }
        __syncthreads();
        float a2[4][4];
        #pragma unroll
        for (int i = 0; i < 4; i++)
            #pragma unroll
            for (int j = 0; j < 4; j++) a2[i][j] = 0.f;
        #pragma unroll 8
        for (int k = 0; k < 64; k++) {
            float p0 = s_sim[(ty*4+0)*66 + k];
            float p1 = s_sim[(ty*4+1)*66 + k];
            float p2 = s_sim[(ty*4+2)*66 + k];
            float p3 = s_sim[(ty*4+3)*66 + k];
            float4 qv = *(float4*)&s_q2[k*68 + tx*4];
            float q4[4] = {qv.x, qv.y, qv.z, qv.w};
            #pragma unroll
            for (int j = 0; j < 4; j++) {
                a2[0][j] += p0 * q4[j];
                a2[1][j] += p1 * q4[j];
                a2[2][j] += p2 * q4[j];
                a2[3][j] += p3 * q4[j];
            }
        }
        #pragma unroll
        for (int i = 0; i < 4; i++) {
            float4 w4 = make_float4(a2[i][0], a2[i][1], a2[i][2], a2[i][3]);
            *(float4*)&g_u[((size_t)b*CC + ct*64 + ty*4 + i)*DD + d0 + tx*4] = w4;
        }
        __syncthreads();
    }
}

// ---------------------------------------------------------------------------
// Kernel 2a: attn softmax over C
// ---------------------------------------------------------------------------
__global__ void k_attn() {
    __shared__ float red[256];
    int b = blockIdx.x, tid = threadIdx.x;
    float v0 = g_m[b*CC + tid], v1 = g_m[b*CC + 256 + tid];
    float mx = fmaxf(v0, v1);
    red[tid] = mx; __syncthreads();
    for (int s = 128; s > 0; s >>= 1) {
        if (tid < s) red[tid] = fmaxf(red[tid], red[tid + s]);
        __syncthreads();
    }
    mx = red[0]; __syncthreads();
    float e0 = __expf(v0 - mx), e1 = __expf(v1 - mx);
    red[tid] = e0 + e1; __syncthreads();
    for (int s = 128; s > 0; s >>= 1) {
        if (tid < s) red[tid] += red[tid + s];
        __syncthreads();
    }
    float inv = 1.f / red[0];
    g_attn[b*CC + tid]       = e0 * inv;
    g_attn[b*CC + 256 + tid] = e1 * inv;
}

// ---------------------------------------------------------------------------
// Kernel 2b: h_tilde — 128 blocks x 128 thr, 2-way c-split per thread
// ---------------------------------------------------------------------------
__global__ void k_h(const float* __restrict__ contexts) {
    __shared__ float sa[CC];
    __shared__ float part[128];
    int b  = blockIdx.x >> 3;
    int dc = blockIdx.x & 7;
    int tid = threadIdx.x;
    int d = dc*64 + (tid & 63);
    int h = tid >> 6;                 // 0/1 -> c half
    for (int i = tid; i < CC; i += 128) sa[i] = g_attn[b*CC + i];
    __syncthreads();
    const float* ctx = contexts + (size_t)b*CC*DD + (size_t)h*256*DD;
    float acc = 0.f;
    #pragma unroll 8
    for (int c = 0; c < 256; c++) acc += sa[h*256 + c] * ctx[(size_t)c*DD + d];
    part[tid] = acc;
    __syncthreads();
    if (h == 0) g_h[b*DD + d] = part[tid] + part[tid + 64];
}

// ---------------------------------------------------------------------------
// Kernel 3: megamerge -> fp16 hi/lo split (A operand of the big GEMM)
// ---------------------------------------------------------------------------
__global__ void k_mm(const float* __restrict__ contexts) {
    size_t i4 = (size_t)blockIdx.x * 256 + threadIdx.x;   // MTOT*D4/4
    int m   = (int)(i4 >> 9);
    int k4  = (int)(i4 & 511);
    int seg = k4 >> 7;
    int off = (k4 & 127) * 4;
    int b   = m >> 9;
    float4 cv = *(const float4*)(contexts + (size_t)m*DD + off);
    float4 r;
    if (seg == 0) {
        r = cv;
    } else if (seg == 3) {
        float4 hv = *(const float4*)(g_h + (size_t)b*DD + off);
        r = make_float4(cv.x*hv.x, cv.y*hv.y, cv.z*hv.z, cv.w*hv.w);
    } else {
        float4 uv = *(const float4*)(g_u + (size_t)m*DD + off);
        r = (seg == 1) ? uv
                       : make_float4(uv.x*cv.x, uv.y*cv.y, uv.z*cv.z, uv.w*cv.w);
    }
    uint2 h4, l4;
    split2h(r.x, r.y, h4.x, l4.x);
    split2h(r.z, r.w, h4.y, l4.y);
    ((uint2*)g_Ahi)[i4] = h4;
    ((uint2*)g_Alo)[i4] = l4;
}

// ---------------------------------------------------------------------------
// Kernel 3b: qac_w -> fp16 (B operand)
// ---------------------------------------------------------------------------
__global__ void k_wsplit(const float* __restrict__ w) {
    size_t i4 = (size_t)blockIdx.x * 256 + threadIdx.x;   // D4*D4/4
    float4 v = ((const float4*)w)[i4];
    uint2 h4;
    __half hx = __float2half_rn(v.x), hy = __float2half_rn(v.y);
    __half hz = __float2half_rn(v.z), hw = __float2half_rn(v.w);
    h4.x = ((uint32_t)__half_as_ushort(hy) << 16) | (uint32_t)__half_as_ushort(hx);
    h4.y = ((uint32_t)__half_as_ushort(hw) << 16) | (uint32_t)__half_as_ushort(hz);
    ((uint2*)g_Bhi)[i4] = h4;
}

// ---------------------------------------------------------------------------
// Kernel 4: mma.sync fp16 GEMM (2-term split, K_eff = 4096)
//   out = Ahi*Bhi^T + Alo*Bhi^T + bias
// CTA tile 128x256, 8 warps (2Mx4N), warp tile 64x64, mma.m16n8k16.
// 32 K-iters of 64; 3-stage cp.async pipeline (73.7 KB/stage).
// ---------------------------------------------------------------------------
#define ROWB 144
#define ATILE (128*ROWB)         // 18432 B
#define BTILE (256*ROWB)         // 36864 B
#define STG3B (2*ATILE + BTILE)  // 73728 B per stage (Ahi|Alo|Bhi)
#define GSMEM2 (3*STG3B)         // 221184 B

__global__ __launch_bounds__(256) void k_gemm_mma(
    const float* __restrict__ bias, float* __restrict__ out) {
    extern __shared__ char smem[];
    uint32_t su = smem_u32(smem);
    int tid  = threadIdx.x;
    int lane = tid & 31;
    int w    = tid >> 5;
    int wm   = w >> 2;          // 0..1 (M 64-half)
    int wn   = w & 3;           // 0..3 (N 64-quarter)
    int n0 = blockIdx.x * 256;
    int m0 = blockIdx.y * 128;

    float acc[4][8][4];
    #pragma unroll
    for (int i = 0; i < 4; i++)
        #pragma unroll
        for (int p = 0; p < 8; p++)
            #pragma unroll
            for (int e = 0; e < 4; e++) acc[i][p][e] = 0.f;

    int lrow = tid >> 3;        // 0..31
    int lchk = tid & 7;         // 16B chunk within 128B row

    auto load_stage = [&](int it, int s) {
        int kbase = it * 64;
        uint32_t sb = su + s*STG3B;
        #pragma unroll
        for (int i = 0; i < 4; i++) {
            int row = lrow + i*32;
            size_t aoff = (size_t)(m0 + row)*D4 + kbase + lchk*8;
            uint32_t d = sb + row*ROWB + lchk*16;
            CP16(d,         (const void*)(g_Ahi + aoff));
            CP16(d + ATILE, (const void*)(g_Alo + aoff));
        }
        #pragma unroll
        for (int i = 0; i < 8; i++) {
            int row = lrow + i*32;
            size_t boff = (size_t)(n0 + row)*D4 + kbase + lchk*8;
            CP16(sb + 2*ATILE + row*ROWB + lchk*16, (const void*)(g_Bhi + boff));
        }
        asm volatile("cp.async.commit_group;" ::: "memory");
    };

    load_stage(0, 0);
    load_stage(1, 1);

    int lr16 = (lane & 7) + ((lane >> 3) & 1) * 8;   // row 0..15
    int lc16 = lane >> 4;                             // chunk 0/1

    for (int it = 0; it < 32; it++) {
        int s = it % 3;
        if (it < 31) {
            asm volatile("cp.async.wait_group %0;" :: "n"(1) : "memory");
        } else {
            asm volatile("cp.async.wait_group %0;" :: "n"(0) : "memory");
        }
        __syncthreads();

        // overlap: kick off stage it+2 before compute (buffer free since it-1)
        if (it + 2 < 32) load_stage(it + 2, (it + 2) % 3);

        uint32_t base = su + s*STG3B;
        uint32_t aW = base + (wm*64 + lr16)*ROWB + lc16*16;
        uint32_t bW = base + 2*ATILE + (wn*64 + lr16)*ROWB + lc16*16;

        #pragma unroll
        for (int j = 0; j < 4; j++) {
            uint32_t afh[4][4], afl[4][4];
            #pragma unroll
            for (int i = 0; i < 4; i++)
                LDSM4(afh[i], aW + i*16*ROWB + j*32);
            #pragma unroll
            for (int i = 0; i < 4; i++)
                LDSM4(afl[i], aW + ATILE + i*16*ROWB + j*32);
            uint32_t bfh[4][4];
            #pragma unroll
            for (int h = 0; h < 4; h++)
                LDSM4(bfh[h], bW + h*16*ROWB + j*32);
            #pragma unroll
            for (int i = 0; i < 4; i++)
                #pragma unroll
                for (int p = 0; p < 8; p++) {
                    uint32_t b0 = bfh[p>>1][p&1], b1 = bfh[p>>1][(p&1)+2];
                    mma16816(acc[i][p], afh[i], b0, b1);
                    mma16816(acc[i][p], afl[i], b0, b1);
                }
        }
    }

    // Epilogue
    int g = lane >> 2, t = lane & 3;
    #pragma unroll
    for (int i = 0; i < 4; i++) {
        int row = m0 + wm*64 + i*16 + g;
        #pragma unroll
        for (int p = 0; p < 8; p++) {
            int col = n0 + wn*64 + p*8 + 2*t;
            float b0 = bias[col], b1 = bias[col + 1];
            float2 v0 = make_float2(acc[i][p][0] + b0, acc[i][p][1] + b1);
            float2 v1 = make_float2(acc[i][p][2] + b0, acc[i][p][3] + b1);
            *(float2*)(out + (size_t)row*D4 + col)       = v0;
            *(float2*)(out + (size_t)(row + 8)*D4 + col) = v1;
        }
    }
}

// ---------------------------------------------------------------------------
extern "C" void kernel_launch(void* const* d_in, const int* in_sizes, int n_in,
                              void* d_out, int out_size) {
    const float* questions = (const float*)d_in[0];
    const float* contexts  = (const float*)d_in[1];
    const float* sim_w     = (const float*)d_in[2];
    const float* qac_w     = (const float*)d_in[3];
    const float* qac_b     = (const float*)d_in[4];
    float* out = (float*)d_out;

    cudaFuncSetAttribute(k_gemm_mma, cudaFuncAttributeMaxDynamicSharedMemorySize, GSMEM2);

    k_wsplit<<<4096, 256>>>(qac_w);
    k_sim_u<<<128, 256>>>(questions, contexts, sim_w);
    k_attn<<<16, 256>>>();
    k_h<<<128, 128>>>(contexts);
    k_mm<<<16384, 256>>>(contexts);
    k_gemm_mma<<<dim3(8, 64), 256, GSMEM2>>>(qac_b, out);
}

// round 7
// speedup vs baseline: 1.6637x; 1.6637x over previous
#include <cuda_runtime.h>
#include <cuda_fp16.h>
#include <math.h>
#include <stdint.h>

// Problem constants
#define BB 16
#define QQ 64
#define CC 512
#define DD 512
#define D4 2048
#define MTOT (BB*CC)   // 8192

// Scratch (device globals: allocation-free rule)
__device__ float g_m[BB*CC];
__device__ float g_attn[BB*CC];
__device__ float g_h[BB*DD];
__device__ float g_u[(size_t)BB*CC*DD];                      // 16.8 MB
__device__ __align__(16) __half g_Ah[(size_t)MTOT*D4];       // 32 MB
__device__ __align__(16) __half g_Bh[(size_t)D4*D4];         // 8 MB

__device__ __forceinline__ uint32_t smem_u32(const void* p) {
    uint32_t a;
    asm("{ .reg .u64 t; cvta.to.shared.u64 t, %1; cvt.u32.u64 %0, t; }"
        : "=r"(a) : "l"(p));
    return a;
}

#define LDSM4(r, addr) \
    asm volatile("ldmatrix.sync.aligned.m8n8.x4.shared.b16 {%0,%1,%2,%3}, [%4];" \
        : "=r"((r)[0]), "=r"((r)[1]), "=r"((r)[2]), "=r"((r)[3]) : "r"(addr))

#define CP16(dst, src) \
    asm volatile("cp.async.cg.shared.global [%0], [%1], 16;" \
        :: "r"(dst), "l"(src) : "memory")

__device__ __forceinline__ void mma16816(float* d, const uint32_t* a,
                                         uint32_t b0, uint32_t b1) {
    asm volatile(
        "mma.sync.aligned.m16n8k16.row.col.f32.f16.f16.f32 "
        "{%0,%1,%2,%3}, {%4,%5,%6,%7}, {%8,%9}, {%0,%1,%2,%3};"
        : "+f"(d[0]), "+f"(d[1]), "+f"(d[2]), "+f"(d[3])
        : "r"(a[0]), "r"(a[1]), "r"(a[2]), "r"(a[3]), "r"(b0), "r"(b1));
}

// ---------------------------------------------------------------------------
// Kernel 1: per (b, 32-c-tile): row-dots + sim tile + softmax + u_tilde
// 256 blocks (16 b x 16 c-tiles), 256 threads
// ---------------------------------------------------------------------------
__global__ __launch_bounds__(256) void k_sim_u(
    const float* __restrict__ questions,
    const float* __restrict__ contexts,
    const float* __restrict__ sim_w) {
    __shared__ float sh[2112 + 4352];   // phase A: s_a(1024)+s_b(2048); B: s_sim 32*66; C: +s_q2 64*68
    __shared__ float s_cq[32], s_qq[64];
    int b  = blockIdx.x >> 4;
    int ct = blockIdx.x & 15;
    int tid = threadIdx.x;
    int tx = tid & 15, ty = tid >> 4;     // ty 0..15 -> 2 c-rows; tx -> 4 q-cols
    int wid = tid >> 5, lane = tid & 31;

    const float* wp  = sim_w + 2*DD;
    const float* ctx = contexts + ((size_t)b*CC + ct*32) * DD;
    const float* qs  = questions + (size_t)b*QQ*DD;

    // Fused row-dots: warps 0-3 -> cq (32 ctx rows), warps 4-7 -> qq (64 q rows)
    if (wid < 4) {
        #pragma unroll
        for (int r = 0; r < 8; r++) {
            int row = wid*8 + r;
            const float* src = ctx + (size_t)row*DD;
            float s = 0.f;
            #pragma unroll 4
            for (int d = lane; d < DD; d += 32) s += src[d] * sim_w[d];
            #pragma unroll
            for (int o = 16; o > 0; o >>= 1) s += __shfl_xor_sync(0xffffffffu, s, o);
            if (lane == 0) s_cq[row] = s;
        }
    } else {
        const float* wq = sim_w + DD;
        #pragma unroll
        for (int r = 0; r < 16; r++) {
            int row = (wid - 4)*16 + r;
            const float* src = qs + (size_t)row*DD;
            float s = 0.f;
            #pragma unroll 4
            for (int d = lane; d < DD; d += 32) s += src[d] * wq[d];
            #pragma unroll
            for (int o = 16; o > 0; o >>= 1) s += __shfl_xor_sync(0xffffffffu, s, o);
            if (lane == 0) s_qq[row] = s;
        }
    }

    float acc[2][4];
    #pragma unroll
    for (int i = 0; i < 2; i++)
        #pragma unroll
        for (int j = 0; j < 4; j++) acc[i][j] = 0.f;

    float* s_a = sh;            // [32k][32row]
    float* s_b = sh + 1024;     // [32k][64row]

    // Phase A: sim[32c x 64q], K=512 in chunks of 32
    for (int k0 = 0; k0 < DD; k0 += 32) {
        __syncthreads();
        {   // A: 32 rows x 8 float4 = 256 loads (one per thread)
            int row = tid >> 3, kq = tid & 7;
            float4 av = *(const float4*)(ctx + (size_t)row*DD + k0 + kq*4);
            float4 wv = *(const float4*)(wp + k0 + kq*4);
            s_a[(kq*4+0)*32 + row] = av.x * wv.x;
            s_a[(kq*4+1)*32 + row] = av.y * wv.y;
            s_a[(kq*4+2)*32 + row] = av.z * wv.z;
            s_a[(kq*4+3)*32 + row] = av.w * wv.w;
        }
        #pragma unroll
        for (int i = 0; i < 2; i++) {   // B: 64 rows x 8 float4 = 512
            int li = tid*2 + i;
            int row = li >> 3, kq = li & 7;
            float4 qv = *(const float4*)(qs + (size_t)row*DD + k0 + kq*4);
            s_b[(kq*4+0)*64 + row] = qv.x;
            s_b[(kq*4+1)*64 + row] = qv.y;
            s_b[(kq*4+2)*64 + row] = qv.z;
            s_b[(kq*4+3)*64 + row] = qv.w;
        }
        __syncthreads();
        #pragma unroll
        for (int k = 0; k < 32; k++) {
            float2 av = *(float2*)&s_a[k*32 + ty*2];
            float4 bv = *(float4*)&s_b[k*64 + tx*4];
            float b4[4] = {bv.x, bv.y, bv.z, bv.w};
            #pragma unroll
            for (int j = 0; j < 4; j++) {
                acc[0][j] += av.x * b4[j];
                acc[1][j] += av.y * b4[j];
            }
        }
    }
    __syncthreads();

    // Phase B: add cq/qq, write sim, per-row softmax (Q=64), rowmax -> g_m
    float* s_sim = sh;          // [32][66]
    #pragma unroll
    for (int i = 0; i < 2; i++) {
        float cqv = s_cq[ty*2 + i];
        #pragma unroll
        for (int j = 0; j < 4; j++)
            s_sim[(ty*2+i)*66 + tx*4 + j] = acc[i][j] + cqv + s_qq[tx*4 + j];
    }
    __syncthreads();

    #pragma unroll
    for (int rr = 0; rr < 4; rr++) {
        int r = wid*4 + rr;
        float v0 = s_sim[r*66 + lane];
        float v1 = s_sim[r*66 + 32 + lane];
        float mx = fmaxf(v0, v1);
        #pragma unroll
        for (int o = 16; o > 0; o >>= 1) mx = fmaxf(mx, __shfl_xor_sync(0xffffffffu, mx, o));
        float e0 = __expf(v0 - mx), e1 = __expf(v1 - mx);
        float sm = e0 + e1;
        #pragma unroll
        for (int o = 16; o > 0; o >>= 1) sm += __shfl_xor_sync(0xffffffffu, sm, o);
        float inv = 1.f / sm;
        s_sim[r*66 + lane]      = e0 * inv;
        s_sim[r*66 + 32 + lane] = e1 * inv;
        if (lane == 0) g_m[b*CC + ct*32 + r] = mx;
    }
    __syncthreads();

    // Phase C: u[32 x 512] = P[32x64] @ qs[64x512]
    float* s_q2 = sh + 2112;    // [64][68]
    for (int d0 = 0; d0 < DD; d0 += 64) {
        #pragma unroll
        for (int i = 0; i < 4; i++) {
            int li  = tid + i*256;
            int row = li >> 4;
            int dq  = li & 15;
            float4 qv = *(const float4*)(qs + (size_t)row*DD + d0 + dq*4);
            *(float4*)&s_q2[row*68 + dq*4] = qv;
        }
        __syncthreads();
        float a2[2][4];
        #pragma unroll
        for (int i = 0; i < 2; i++)
            #pragma unroll
            for (int j = 0; j < 4; j++) a2[i][j] = 0.f;
        #pragma unroll 8
        for (int k = 0; k < 64; k++) {
            float p0 = s_sim[(ty*2+0)*66 + k];
            float p1 = s_sim[(ty*2+1)*66 + k];
            float4 qv = *(float4*)&s_q2[k*68 + tx*4];
            float q4[4] = {qv.x, qv.y, qv.z, qv.w};
            #pragma unroll
            for (int j = 0; j < 4; j++) {
                a2[0][j] += p0 * q4[j];
                a2[1][j] += p1 * q4[j];
            }
        }
        #pragma unroll
        for (int i = 0; i < 2; i++) {
            float4 w4 = make_float4(a2[i][0], a2[i][1], a2[i][2], a2[i][3]);
            *(float4*)&g_u[((size_t)b*CC + ct*32 + ty*2 + i)*DD + d0 + tx*4] = w4;
        }
        __syncthreads();
    }
}

// ---------------------------------------------------------------------------
// Kernel 2a: attn softmax over C
// ---------------------------------------------------------------------------
__global__ void k_attn() {
    __shared__ float red[256];
    int b = blockIdx.x, tid = threadIdx.x;
    float v0 = g_m[b*CC + tid], v1 = g_m[b*CC + 256 + tid];
    float mx = fmaxf(v0, v1);
    red[tid] = mx; __syncthreads();
    for (int s = 128; s > 0; s >>= 1) {
        if (tid < s) red[tid] = fmaxf(red[tid], red[tid + s]);
        __syncthreads();
    }
    mx = red[0]; __syncthreads();
    float e0 = __expf(v0 - mx), e1 = __expf(v1 - mx);
    red[tid] = e0 + e1; __syncthreads();
    for (int s = 128; s > 0; s >>= 1) {
        if (tid < s) red[tid] += red[tid + s];
        __syncthreads();
    }
    float inv = 1.f / red[0];
    g_attn[b*CC + tid]       = e0 * inv;
    g_attn[b*CC + 256 + tid] = e1 * inv;
}

// ---------------------------------------------------------------------------
// Kernel 2b: h_tilde — 128 blocks x 128 thr, 2-way c-split per thread
// ---------------------------------------------------------------------------
__global__ void k_h(const float* __restrict__ contexts) {
    __shared__ float sa[CC];
    __shared__ float part[128];
    int b  = blockIdx.x >> 3;
    int dc = blockIdx.x & 7;
    int tid = threadIdx.x;
    int d = dc*64 + (tid & 63);
    int h = tid >> 6;                 // 0/1 -> c half
    for (int i = tid; i < CC; i += 128) sa[i] = g_attn[b*CC + i];
    __syncthreads();
    const float* ctx = contexts + (size_t)b*CC*DD + (size_t)h*256*DD;
    float acc = 0.f;
    #pragma unroll 8
    for (int c = 0; c < 256; c++) acc += sa[h*256 + c] * ctx[(size_t)c*DD + d];
    part[tid] = acc;
    __syncthreads();
    if (h == 0) g_h[b*DD + d] = part[tid] + part[tid + 64];
}

// ---------------------------------------------------------------------------
// Kernel 3: megamerge -> fp16 (A operand of the big GEMM, single term)
// ---------------------------------------------------------------------------
__global__ void k_mm(const float* __restrict__ contexts) {
    size_t i4 = (size_t)blockIdx.x * 256 + threadIdx.x;   // MTOT*D4/4
    int m   = (int)(i4 >> 9);
    int k4  = (int)(i4 & 511);
    int seg = k4 >> 7;
    int off = (k4 & 127) * 4;
    int b   = m >> 9;
    float4 cv = *(const float4*)(contexts + (size_t)m*DD + off);
    float4 r;
    if (seg == 0) {
        r = cv;
    } else if (seg == 3) {
        float4 hv = *(const float4*)(g_h + (size_t)b*DD + off);
        r = make_float4(cv.x*hv.x, cv.y*hv.y, cv.z*hv.z, cv.w*hv.w);
    } else {
        float4 uv = *(const float4*)(g_u + (size_t)m*DD + off);
        r = (seg == 1) ? uv
                       : make_float4(uv.x*cv.x, uv.y*cv.y, uv.z*cv.z, uv.w*cv.w);
    }
    uint2 h4;
    __half hx = __float2half_rn(r.x), hy = __float2half_rn(r.y);
    __half hz = __float2half_rn(r.z), hw = __float2half_rn(r.w);
    h4.x = ((uint32_t)__half_as_ushort(hy) << 16) | (uint32_t)__half_as_ushort(hx);
    h4.y = ((uint32_t)__half_as_ushort(hw) << 16) | (uint32_t)__half_as_ushort(hz);
    ((uint2*)g_Ah)[i4] = h4;
}

// ---------------------------------------------------------------------------
// Kernel 3b: qac_w -> fp16 (B operand)
// ---------------------------------------------------------------------------
__global__ void k_wsplit(const float* __restrict__ w) {
    size_t i4 = (size_t)blockIdx.x * 256 + threadIdx.x;   // D4*D4/4
    float4 v = ((const float4*)w)[i4];
    uint2 h4;
    __half hx = __float2half_rn(v.x), hy = __float2half_rn(v.y);
    __half hz = __float2half_rn(v.z), hw = __float2half_rn(v.w);
    h4.x = ((uint32_t)__half_as_ushort(hy) << 16) | (uint32_t)__half_as_ushort(hx);
    h4.y = ((uint32_t)__half_as_ushort(hw) << 16) | (uint32_t)__half_as_ushort(hz);
    ((uint2*)g_Bh)[i4] = h4;
}

// ---------------------------------------------------------------------------
// Kernel 4: mma.sync fp16 GEMM (single term, K = 2048)
//   out = Ah*Bh^T + bias     (err ~ 3e-4: A*Blo + Alo*B dropped)
// CTA tile 128x128, 8 warps (2Mx4N), warp tile 64x32, mma.m16n8k16.
// 32 K-iters of 64; 3-stage cp.async pipeline (36.9 KB/stage) -> 2 CTAs/SM.
// ---------------------------------------------------------------------------
#define ROWB 144
#define ATILE (128*ROWB)         // 18432 B
#define STG1B (2*ATILE)          // 36864 B per stage (A|B)
#define GSMEM2 (3*STG1B)         // 110592 B

__global__ __launch_bounds__(256, 2) void k_gemm_mma(
    const float* __restrict__ bias, float* __restrict__ out) {
    extern __shared__ char smem[];
    uint32_t su = smem_u32(smem);
    int tid  = threadIdx.x;
    int lane = tid & 31;
    int w    = tid >> 5;
    int wm   = w >> 2;          // 0..1
    int wn   = w & 3;           // 0..3
    int n0 = blockIdx.x * 128;
    int m0 = blockIdx.y * 128;

    float acc[4][4][4];
    #pragma unroll
    for (int i = 0; i < 4; i++)
        #pragma unroll
        for (int p = 0; p < 4; p++)
            #pragma unroll
            for (int e = 0; e < 4; e++) acc[i][p][e] = 0.f;

    int lrow = tid >> 3;        // 0..31
    int lchk = tid & 7;         // 16B chunk within 128B row

    auto load_stage = [&](int it, int s) {
        int kbase = it * 64;
        uint32_t sb = su + s*STG1B;
        #pragma unroll
        for (int i = 0; i < 4; i++) {
            int row = lrow + i*32;
            size_t aoff = (size_t)(m0 + row)*D4 + kbase + lchk*8;
            size_t boff = (size_t)(n0 + row)*D4 + kbase + lchk*8;
            uint32_t d = sb + row*ROWB + lchk*16;
            CP16(d,         (const void*)(g_Ah + aoff));
            CP16(d + ATILE, (const void*)(g_Bh + boff));
        }
        asm volatile("cp.async.commit_group;" ::: "memory");
    };

    load_stage(0, 0);
    load_stage(1, 1);

    int lr16 = (lane & 7) + ((lane >> 3) & 1) * 8;   // row 0..15
    int lc16 = lane >> 4;                             // chunk 0/1

    for (int it = 0; it < 32; it++) {
        int s = it % 3;
        if (it < 31) {
            asm volatile("cp.async.wait_group %0;" :: "n"(1) : "memory");
        } else {
            asm volatile("cp.async.wait_group %0;" :: "n"(0) : "memory");
        }
        __syncthreads();

        if (it + 2 < 32) load_stage(it + 2, (it + 2) % 3);

        uint32_t base = su + s*STG1B;
        uint32_t aW = base + (wm*64 + lr16)*ROWB + lc16*16;
        uint32_t bW = base + ATILE + (wn*32 + lr16)*ROWB + lc16*16;

        #pragma unroll
        for (int j = 0; j < 4; j++) {
            uint32_t af[4][4];
            #pragma unroll
            for (int i = 0; i < 4; i++)
                LDSM4(af[i], aW + i*16*ROWB + j*32);
            uint32_t bf[2][4];
            #pragma unroll
            for (int h = 0; h < 2; h++)
                LDSM4(bf[h], bW + h*16*ROWB + j*32);
            #pragma unroll
            for (int i = 0; i < 4; i++)
                #pragma unroll
                for (int p = 0; p < 4; p++)
                    mma16816(acc[i][p], af[i], bf[p>>1][p&1], bf[p>>1][(p&1)+2]);
        }
    }

    // Epilogue
    int g = lane >> 2, t = lane & 3;
    #pragma unroll
    for (int i = 0; i < 4; i++) {
        int row = m0 + wm*64 + i*16 + g;
        #pragma unroll
        for (int p = 0; p < 4; p++) {
            int col = n0 + wn*32 + p*8 + 2*t;
            float b0 = bias[col], b1 = bias[col + 1];
            float2 v0 = make_float2(acc[i][p][0] + b0, acc[i][p][1] + b1);
            float2 v1 = make_float2(acc[i][p][2] + b0, acc[i][p][3] + b1);
            *(float2*)(out + (size_t)row*D4 + col)       = v0;
            *(float2*)(out + (size_t)(row + 8)*D4 + col) = v1;
        }
    }
}

// ---------------------------------------------------------------------------
extern "C" void kernel_launch(void* const* d_in, const int* in_sizes, int n_in,
                              void* d_out, int out_size) {
    const float* questions = (const float*)d_in[0];
    const float* contexts  = (const float*)d_in[1];
    const float* sim_w     = (const float*)d_in[2];
    const float* qac_w     = (const float*)d_in[3];
    const float* qac_b     = (const float*)d_in[4];
    float* out = (float*)d_out;

    cudaFuncSetAttribute(k_gemm_mma, cudaFuncAttributeMaxDynamicSharedMemorySize, GSMEM2);

    k_wsplit<<<4096, 256>>>(qac_w);
    k_sim_u<<<256, 256>>>(questions, contexts, sim_w);
    k_attn<<<16, 256>>>();
    k_h<<<128, 128>>>(contexts);
    k_mm<<<16384, 256>>>(contexts);
    k_gemm_mma<<<dim3(16, 64), 256, GSMEM2>>>(qac_b, out);
}

// round 8
// speedup vs baseline: 1.8712x; 1.1247x over previous
#include <cuda_runtime.h>
#include <cuda_fp16.h>
#include <math.h>
#include <stdint.h>

// Problem constants
#define BB 16
#define QQ 64
#define CC 512
#define DD 512
#define D4 2048
#define MTOT (BB*CC)   // 8192

// Scratch (device globals: allocation-free rule)
__device__ float g_m[BB*CC];
__device__ float g_attn[BB*CC];
__device__ float g_hp[4*BB*DD];                              // h partials (4-way c-split)
__device__ __align__(16) __half g_Ah[(size_t)MTOT*D4];       // 32 MB
__device__ __align__(16) __half g_Bh[(size_t)D4*D4];         // 8 MB

__device__ __forceinline__ uint32_t smem_u32(const void* p) {
    uint32_t a;
    asm("{ .reg .u64 t; cvta.to.shared.u64 t, %1; cvt.u32.u64 %0, t; }"
        : "=r"(a) : "l"(p));
    return a;
}

#define LDSM4(r, addr) \
    asm volatile("ldmatrix.sync.aligned.m8n8.x4.shared.b16 {%0,%1,%2,%3}, [%4];" \
        : "=r"((r)[0]), "=r"((r)[1]), "=r"((r)[2]), "=r"((r)[3]) : "r"(addr))

#define CP16(dst, src) \
    asm volatile("cp.async.cg.shared.global [%0], [%1], 16;" \
        :: "r"(dst), "l"(src) : "memory")

__device__ __forceinline__ void mma16816(float* d, const uint32_t* a,
                                         uint32_t b0, uint32_t b1) {
    asm volatile(
        "mma.sync.aligned.m16n8k16.row.col.f32.f16.f16.f32 "
        "{%0,%1,%2,%3}, {%4,%5,%6,%7}, {%8,%9}, {%0,%1,%2,%3};"
        : "+f"(d[0]), "+f"(d[1]), "+f"(d[2]), "+f"(d[3])
        : "r"(a[0]), "r"(a[1]), "r"(a[2]), "r"(a[3]), "r"(b0), "r"(b1));
}

__device__ __forceinline__ uint32_t pack2h(float x, float y) {
    __half hx = __float2half_rn(x), hy = __float2half_rn(y);
    return ((uint32_t)__half_as_ushort(hy) << 16) | (uint32_t)__half_as_ushort(hx);
}

// ---------------------------------------------------------------------------
// Kernel 1: per (b, 32-c-tile): sim tile (+fused row-dots) + softmax + u_tilde
// writes u (seg1) and u*ctx (seg2) of g_Ah directly as fp16.
// 256 blocks (16 b x 16 c-tiles), 256 threads
// ---------------------------------------------------------------------------
__global__ __launch_bounds__(256) void k_sim_u(
    const float* __restrict__ questions,
    const float* __restrict__ contexts,
    const float* __restrict__ sim_w) {
    __shared__ float sh[2112 + 4352];
    __shared__ float s_cq[32], s_qq[64];
    int b  = blockIdx.x >> 4;
    int ct = blockIdx.x & 15;
    int tid = threadIdx.x;
    int tx = tid & 15, ty = tid >> 4;     // ty 0..15 -> 2 c-rows; tx -> 4 q-cols
    int wid = tid >> 5, lane = tid & 31;

    const float* wp  = sim_w + 2*DD;
    const float* wq  = sim_w + DD;
    const float* ctx = contexts + ((size_t)b*CC + ct*32) * DD;
    const float* qs  = questions + (size_t)b*QQ*DD;

    float acc[2][4];
    #pragma unroll
    for (int i = 0; i < 2; i++)
        #pragma unroll
        for (int j = 0; j < 4; j++) acc[i][j] = 0.f;

    float* s_a = sh;            // [32k][32row]
    float* s_b = sh + 1024;     // [32k][64row]

    float cqp = 0.f;            // partial ctx . w_c   (row = tid>>3, kq = tid&7)
    float qqp = 0.f;            // partial q . w_q     (row = tid>>2)

    // Phase A: sim[32c x 64q], K=512 in chunks of 32; row-dots fused into loads
    for (int k0 = 0; k0 < DD; k0 += 32) {
        __syncthreads();
        {   // A: 32 rows x 8 float4 (one per thread)
            int row = tid >> 3, kq = tid & 7;
            float4 av = *(const float4*)(ctx + (size_t)row*DD + k0 + kq*4);
            float4 wv = *(const float4*)(wp + k0 + kq*4);
            float4 wc = *(const float4*)(sim_w + k0 + kq*4);
            cqp += av.x*wc.x + av.y*wc.y + av.z*wc.z + av.w*wc.w;
            s_a[(kq*4+0)*32 + row] = av.x * wv.x;
            s_a[(kq*4+1)*32 + row] = av.y * wv.y;
            s_a[(kq*4+2)*32 + row] = av.z * wv.z;
            s_a[(kq*4+3)*32 + row] = av.w * wv.w;
        }
        #pragma unroll
        for (int i = 0; i < 2; i++) {   // B: 64 rows x 8 float4
            int li = tid*2 + i;
            int row = li >> 3, kq = li & 7;
            float4 qv = *(const float4*)(qs + (size_t)row*DD + k0 + kq*4);
            float4 wv = *(const float4*)(wq + k0 + kq*4);
            qqp += qv.x*wv.x + qv.y*wv.y + qv.z*wv.z + qv.w*wv.w;
            s_b[(kq*4+0)*64 + row] = qv.x;
            s_b[(kq*4+1)*64 + row] = qv.y;
            s_b[(kq*4+2)*64 + row] = qv.z;
            s_b[(kq*4+3)*64 + row] = qv.w;
        }
        __syncthreads();
        #pragma unroll
        for (int k = 0; k < 32; k++) {
            float2 av = *(float2*)&s_a[k*32 + ty*2];
            float4 bv = *(float4*)&s_b[k*64 + tx*4];
            float b4[4] = {bv.x, bv.y, bv.z, bv.w};
            #pragma unroll
            for (int j = 0; j < 4; j++) {
                acc[0][j] += av.x * b4[j];
                acc[1][j] += av.y * b4[j];
            }
        }
    }

    // Reduce fused row-dots: cq (8 lanes/row), qq (4 lanes/row)
    {
        float s = cqp;
        s += __shfl_xor_sync(0xffffffffu, s, 1);
        s += __shfl_xor_sync(0xffffffffu, s, 2);
        s += __shfl_xor_sync(0xffffffffu, s, 4);
        if ((tid & 7) == 0) s_cq[tid >> 3] = s;
        float t = qqp;
        t += __shfl_xor_sync(0xffffffffu, t, 1);
        t += __shfl_xor_sync(0xffffffffu, t, 2);
        if ((tid & 3) == 0) s_qq[tid >> 2] = t;
    }
    __syncthreads();

    // Phase B: add cq/qq, write sim, per-row softmax (Q=64), rowmax -> g_m
    float* s_sim = sh;          // [32][66]
    #pragma unroll
    for (int i = 0; i < 2; i++) {
        float cqv = s_cq[ty*2 + i];
        #pragma unroll
        for (int j = 0; j < 4; j++)
            s_sim[(ty*2+i)*66 + tx*4 + j] = acc[i][j] + cqv + s_qq[tx*4 + j];
    }
    __syncthreads();

    #pragma unroll
    for (int rr = 0; rr < 4; rr++) {
        int r = wid*4 + rr;
        float v0 = s_sim[r*66 + lane];
        float v1 = s_sim[r*66 + 32 + lane];
        float mx = fmaxf(v0, v1);
        #pragma unroll
        for (int o = 16; o > 0; o >>= 1) mx = fmaxf(mx, __shfl_xor_sync(0xffffffffu, mx, o));
        float e0 = __expf(v0 - mx), e1 = __expf(v1 - mx);
        float sm = e0 + e1;
        #pragma unroll
        for (int o = 16; o > 0; o >>= 1) sm += __shfl_xor_sync(0xffffffffu, sm, o);
        float inv = 1.f / sm;
        s_sim[r*66 + lane]      = e0 * inv;
        s_sim[r*66 + 32 + lane] = e1 * inv;
        if (lane == 0) g_m[b*CC + ct*32 + r] = mx;
    }
    __syncthreads();

    // Phase C: u[32 x 512] = P[32x64] @ qs[64x512]; write fp16 seg1/seg2 of A
    float* s_q2 = sh + 2112;    // [64][68]
    for (int d0 = 0; d0 < DD; d0 += 64) {
        #pragma unroll
        for (int i = 0; i < 4; i++) {
            int li  = tid + i*256;
            int row = li >> 4;
            int dq  = li & 15;
            float4 qv = *(const float4*)(qs + (size_t)row*DD + d0 + dq*4);
            *(float4*)&s_q2[row*68 + dq*4] = qv;
        }
        __syncthreads();
        float a2[2][4];
        #pragma unroll
        for (int i = 0; i < 2; i++)
            #pragma unroll
            for (int j = 0; j < 4; j++) a2[i][j] = 0.f;
        #pragma unroll 8
        for (int k = 0; k < 64; k++) {
            float p0 = s_sim[(ty*2+0)*66 + k];
            float p1 = s_sim[(ty*2+1)*66 + k];
            float4 qv = *(float4*)&s_q2[k*68 + tx*4];
            float q4[4] = {qv.x, qv.y, qv.z, qv.w};
            #pragma unroll
            for (int j = 0; j < 4; j++) {
                a2[0][j] += p0 * q4[j];
                a2[1][j] += p1 * q4[j];
            }
        }
        #pragma unroll
        for (int i = 0; i < 2; i++) {
            int lrow = ty*2 + i;
            size_t m = (size_t)b*CC + ct*32 + lrow;
            float4 cv = *(const float4*)(ctx + (size_t)lrow*DD + d0 + tx*4);
            uint2 uh, uc;
            uh.x = pack2h(a2[i][0], a2[i][1]);
            uh.y = pack2h(a2[i][2], a2[i][3]);
            uc.x = pack2h(a2[i][0]*cv.x, a2[i][1]*cv.y);
            uc.y = pack2h(a2[i][2]*cv.z, a2[i][3]*cv.w);
            *(uint2*)&g_Ah[m*D4 + 512  + d0 + tx*4] = uh;
            *(uint2*)&g_Ah[m*D4 + 1024 + d0 + tx*4] = uc;
        }
        __syncthreads();
    }
}

// ---------------------------------------------------------------------------
// Kernel 2a: attn softmax over C
// ---------------------------------------------------------------------------
__global__ void k_attn() {
    __shared__ float red[256];
    int b = blockIdx.x, tid = threadIdx.x;
    float v0 = g_m[b*CC + tid], v1 = g_m[b*CC + 256 + tid];
    float mx = fmaxf(v0, v1);
    red[tid] = mx; __syncthreads();
    for (int s = 128; s > 0; s >>= 1) {
        if (tid < s) red[tid] = fmaxf(red[tid], red[tid + s]);
        __syncthreads();
    }
    mx = red[0]; __syncthreads();
    float e0 = __expf(v0 - mx), e1 = __expf(v1 - mx);
    red[tid] = e0 + e1; __syncthreads();
    for (int s = 128; s > 0; s >>= 1) {
        if (tid < s) red[tid] += red[tid + s];
        __syncthreads();
    }
    float inv = 1.f / red[0];
    g_attn[b*CC + tid]       = e0 * inv;
    g_attn[b*CC + 256 + tid] = e1 * inv;
}

// ---------------------------------------------------------------------------
// Kernel 2b: h_tilde partials — 512 blocks (b x 8 dchunk x 4 csplit) x 128 thr
// ---------------------------------------------------------------------------
__global__ void k_h(const float* __restrict__ contexts) {
    __shared__ float sa[128];
    __shared__ float part[128];
    int bid = blockIdx.x;
    int cs = bid & 3;
    int dc = (bid >> 2) & 7;
    int b  = bid >> 5;
    int tid = threadIdx.x;
    int d = dc*64 + (tid & 63);
    int h = tid >> 6;                  // 0/1 -> 64-c subhalf
    sa[tid] = g_attn[b*CC + cs*128 + tid];
    __syncthreads();
    const float* ctx = contexts + ((size_t)b*CC + cs*128 + h*64)*DD;
    float acc = 0.f;
    #pragma unroll 8
    for (int c = 0; c < 64; c++) acc += sa[h*64 + c] * ctx[(size_t)c*DD + d];
    part[tid] = acc;
    __syncthreads();
    if (h == 0) g_hp[((size_t)b*4 + cs)*DD + d] = part[tid] + part[tid + 64];
}

// ---------------------------------------------------------------------------
// Kernel 3: A seg0/seg3 -> fp16, and qac_w -> fp16 (merged)
// blocks 0..8191: one A row each (threads 0-127 seg0, 128-255 seg3)
// blocks 8192..12287: wsplit
// ---------------------------------------------------------------------------
__global__ void k_mm(const float* __restrict__ contexts,
                     const float* __restrict__ qac_w) {
    int bid = blockIdx.x;
    int tid = threadIdx.x;
    if (bid < 8192) {
        int m = bid;
        int b = m >> 9;
        uint2 h4;
        if (tid < 128) {
            int off = tid*4;
            float4 cv = *(const float4*)(contexts + (size_t)m*DD + off);
            h4.x = pack2h(cv.x, cv.y);
            h4.y = pack2h(cv.z, cv.w);
            *(uint2*)&g_Ah[(size_t)m*D4 + off] = h4;
        } else {
            int off = (tid - 128)*4;
            float4 cv = *(const float4*)(contexts + (size_t)m*DD + off);
            const float* hp = g_hp + (size_t)b*4*DD + off;
            float4 h0 = *(const float4*)(hp);
            float4 h1 = *(const float4*)(hp + DD);
            float4 h2 = *(const float4*)(hp + 2*DD);
            float4 h3 = *(const float4*)(hp + 3*DD);
            float hx = h0.x+h1.x+h2.x+h3.x;
            float hy = h0.y+h1.y+h2.y+h3.y;
            float hz = h0.z+h1.z+h2.z+h3.z;
            float hw = h0.w+h1.w+h2.w+h3.w;
            h4.x = pack2h(cv.x*hx, cv.y*hy);
            h4.y = pack2h(cv.z*hz, cv.w*hw);
            *(uint2*)&g_Ah[(size_t)m*D4 + 1536 + off] = h4;
        }
    } else {
        size_t i4 = (size_t)(bid - 8192)*256 + tid;   // D4*D4/4
        float4 v = ((const float4*)qac_w)[i4];
        uint2 h4;
        h4.x = pack2h(v.x, v.y);
        h4.y = pack2h(v.z, v.w);
        ((uint2*)g_Bh)[i4] = h4;
    }
}

// ---------------------------------------------------------------------------
// Kernel 4: mma.sync fp16 GEMM (single term, K = 2048)  [R7, unchanged]
// ---------------------------------------------------------------------------
#define ROWB 144
#define ATILE (128*ROWB)         // 18432 B
#define STG1B (2*ATILE)          // 36864 B per stage (A|B)
#define GSMEM2 (3*STG1B)         // 110592 B

__global__ __launch_bounds__(256, 2) void k_gemm_mma(
    const float* __restrict__ bias, float* __restrict__ out) {
    extern __shared__ char smem[];
    uint32_t su = smem_u32(smem);
    int tid  = threadIdx.x;
    int lane = tid & 31;
    int w    = tid >> 5;
    int wm   = w >> 2;          // 0..1
    int wn   = w & 3;           // 0..3
    int n0 = blockIdx.x * 128;
    int m0 = blockIdx.y * 128;

    float acc[4][4][4];
    #pragma unroll
    for (int i = 0; i < 4; i++)
        #pragma unroll
        for (int p = 0; p < 4; p++)
            #pragma unroll
            for (int e = 0; e < 4; e++) acc[i][p][e] = 0.f;

    int lrow = tid >> 3;        // 0..31
    int lchk = tid & 7;         // 16B chunk within 128B row

    auto load_stage = [&](int it, int s) {
        int kbase = it * 64;
        uint32_t sb = su + s*STG1B;
        #pragma unroll
        for (int i = 0; i < 4; i++) {
            int row = lrow + i*32;
            size_t aoff = (size_t)(m0 + row)*D4 + kbase + lchk*8;
            size_t boff = (size_t)(n0 + row)*D4 + kbase + lchk*8;
            uint32_t d = sb + row*ROWB + lchk*16;
            CP16(d,         (const void*)(g_Ah + aoff));
            CP16(d + ATILE, (const void*)(g_Bh + boff));
        }
        asm volatile("cp.async.commit_group;" ::: "memory");
    };

    load_stage(0, 0);
    load_stage(1, 1);

    int lr16 = (lane & 7) + ((lane >> 3) & 1) * 8;   // row 0..15
    int lc16 = lane >> 4;                             // chunk 0/1

    for (int it = 0; it < 32; it++) {
        int s = it % 3;
        if (it < 31) {
            asm volatile("cp.async.wait_group %0;" :: "n"(1) : "memory");
        } else {
            asm volatile("cp.async.wait_group %0;" :: "n"(0) : "memory");
        }
        __syncthreads();

        if (it + 2 < 32) load_stage(it + 2, (it + 2) % 3);

        uint32_t base = su + s*STG1B;
        uint32_t aW = base + (wm*64 + lr16)*ROWB + lc16*16;
        uint32_t bW = base + ATILE + (wn*32 + lr16)*ROWB + lc16*16;

        #pragma unroll
        for (int j = 0; j < 4; j++) {
            uint32_t af[4][4];
            #pragma unroll
            for (int i = 0; i < 4; i++)
                LDSM4(af[i], aW + i*16*ROWB + j*32);
            uint32_t bf[2][4];
            #pragma unroll
            for (int h = 0; h < 2; h++)
                LDSM4(bf[h], bW + h*16*ROWB + j*32);
            #pragma unroll
            for (int i = 0; i < 4; i++)
                #pragma unroll
                for (int p = 0; p < 4; p++)
                    mma16816(acc[i][p], af[i], bf[p>>1][p&1], bf[p>>1][(p&1)+2]);
        }
    }

    // Epilogue
    int g = lane >> 2, t = lane & 3;
    #pragma unroll
    for (int i = 0; i < 4; i++) {
        int row = m0 + wm*64 + i*16 + g;
        #pragma unroll
        for (int p = 0; p < 4; p++) {
            int col = n0 + wn*32 + p*8 + 2*t;
            float b0 = bias[col], b1 = bias[col + 1];
            float2 v0 = make_float2(acc[i][p][0] + b0, acc[i][p][1] + b1);
            float2 v1 = make_float2(acc[i][p][2] + b0, acc[i][p][3] + b1);
            *(float2*)(out + (size_t)row*D4 + col)       = v0;
            *(float2*)(out + (size_t)(row + 8)*D4 + col) = v1;
        }
    }
}

// ---------------------------------------------------------------------------
extern "C" void kernel_launch(void* const* d_in, const int* in_sizes, int n_in,
                              void* d_out, int out_size) {
    const float* questions = (const float*)d_in[0];
    const float* contexts  = (const float*)d_in[1];
    const float* sim_w     = (const float*)d_in[2];
    const float* qac_w     = (const float*)d_in[3];
    const float* qac_b     = (const float*)d_in[4];
    float* out = (float*)d_out;

    cudaFuncSetAttribute(k_gemm_mma, cudaFuncAttributeMaxDynamicSharedMemorySize, GSMEM2);

    k_sim_u<<<256, 256>>>(questions, contexts, sim_w);
    k_attn<<<16, 256>>>();
    k_h<<<512, 128>>>(contexts);
    k_mm<<<12288, 256>>>(contexts, qac_w);
    k_gemm_mma<<<dim3(16, 64), 256, GSMEM2>>>(qac_b, out);
}